// round 9
// baseline (speedup 1.0000x reference)
#include <cuda_runtime.h>

// E8 quantizer, closed form, f32x2-packed WITHIN a point (1 point/thread).
//
// Math (rounds 1-7): all 240 E8 roots have ||c||^2 = 2, so the softmax over
// -(dist^2)/T reduces to softmax(beta * x.c), beta = 2/0.3, and factorizes:
//  Type-1 (112 roots, +-1 at dims i,j):  A_i = 2cosh(beta x_i)
//     denom1 = sum_{i<j} A_i A_j,  num1_d = (a_d b_d) * exclSum_d(A)
//  Type-2 (128 roots, (+-1/2)^8, even parity): a_i = 2cosh(bx_i/2), b_i = 2sinh(bx_i/2)
//     denom2 = (prod a + prod b)/2, num2_d = (b_d exclProd_d(a) + a_d exclProd_d(b))/4
//  with A = a^2 - 2.  16 EX2 + 1 RCP per point.  All-positive adds /
//  sign-safe muls -> no cancellation; +- root pairs => denom >= 1.
//
// R5 lesson: packing two POINTS doubles registers -> occupancy collapse.
// This round packs dims (d, d+4) of the SAME point into one f32x2 register:
// identical live state to scalar (8 floats = 4 reg-pairs), but elementwise
// math and the per-half trees run on the packed FFMA2 pipe (PTX f32x2) at
// half the instruction count.  Cross-half terms use a 64-bit half-swap
// (2 ALU movs) instead of shuffles; denominator computed once per thread.
// Persistent single wave + double-buffered prefetch (R4 winner) retained.

#define BETA_HALF_LOG2E 4.8089834696568576f   // (2/0.3)/2 * log2(e)

typedef unsigned long long u64;

__device__ __forceinline__ float ex2_approx(float x) {
    float y; asm("ex2.approx.ftz.f32 %0, %1;" : "=f"(y) : "f"(x)); return y;
}
__device__ __forceinline__ float rcp_approx(float x) {
    float y; asm("rcp.approx.ftz.f32 %0, %1;" : "=f"(y) : "f"(x)); return y;
}
__device__ __forceinline__ u64 pk(float lo, float hi) {
    u64 r; asm("mov.b64 %0, {%1, %2};" : "=l"(r) : "f"(lo), "f"(hi)); return r;
}
__device__ __forceinline__ void upk(float& lo, float& hi, u64 v) {
    asm("mov.b64 {%0, %1}, %2;" : "=f"(lo), "=f"(hi) : "l"(v));
}
__device__ __forceinline__ u64 swap64(u64 v) {           // (lo,hi) -> (hi,lo)
    float lo, hi; upk(lo, hi, v); return pk(hi, lo);
}
__device__ __forceinline__ u64 f2fma(u64 a, u64 b, u64 c) {
    u64 r; asm("fma.rn.f32x2 %0, %1, %2, %3;" : "=l"(r) : "l"(a), "l"(b), "l"(c)); return r;
}
__device__ __forceinline__ u64 f2add(u64 a, u64 b) {
    u64 r; asm("add.rn.f32x2 %0, %1, %2;" : "=l"(r) : "l"(a), "l"(b)); return r;
}
__device__ __forceinline__ u64 f2mul(u64 a, u64 b) {
    u64 r; asm("mul.rn.f32x2 %0, %1, %2;" : "=l"(r) : "l"(a), "l"(b)); return r;
}

__global__ void __launch_bounds__(256) e8_quantize_kernel(
    const float4* __restrict__ x4, float4* __restrict__ o4, int n, int stride)
{
    const u64 cBp = pk( BETA_HALF_LOG2E,  BETA_HALF_LOG2E);
    const u64 cBn = pk(-BETA_HALF_LOG2E, -BETA_HALF_LOG2E);
    const u64 cN2 = pk(-2.0f, -2.0f);
    const u64 cQ  = pk(0.25f, 0.25f);

    int p = blockIdx.x * blockDim.x + threadIdx.x;
    if (p >= n) return;

    float4 v0 = x4[2 * p + 0];
    float4 v1 = x4[2 * p + 1];

    for (;;) {
        int pn = p + stride;
        bool more = pn < n;
        float4 w0, w1;
        if (more) { w0 = x4[2 * pn + 0]; w1 = x4[2 * pn + 1]; }  // prefetch

        // pack dims (d, d+4); SASS reg-pairs make pk of fresh scalars ~free
        u64 X[4] = { pk(v0.x, v1.x), pk(v0.y, v1.y), pk(v0.z, v1.z), pk(v0.w, v1.w) };

        u64 a[4], b[4], A[4];
#pragma unroll
        for (int i = 0; i < 4; i++) {
            u64 tp = f2mul(X[i], cBp);
            u64 tn = f2mul(X[i], cBn);
            float tpl, tph, tnl, tnh;
            upk(tpl, tph, tp); upk(tnl, tnh, tn);
            u64 hp = pk(ex2_approx(tpl), ex2_approx(tph));
            u64 hn = pk(ex2_approx(tnl), ex2_approx(tnh));
            a[i] = f2add(hp, hn);                    // 2cosh(beta x / 2)
            b[i] = f2fma(hn, pk(-1.0f, -1.0f), hp);  // 2sinh(beta x / 2)
            A[i] = f2fma(a[i], a[i], cN2);           // 2cosh(beta x)
        }

        // ---- per-half trees over the 4 packed elements ----
        // sums of A (lo lane: dims 0-3; hi lane: dims 4-7), all positive
        u64 s01 = f2add(A[0], A[1]), s23 = f2add(A[2], A[3]);
        u64 S = f2add(s01, s23);                     // (S_lo, S_hi)
        u64 eo[4] = { f2add(A[1], s23), f2add(A[0], s23),
                      f2add(s01, A[3]), f2add(s01, A[2]) };  // excl-within-half

        // within-half pair sums: sig = A0A1 + A2A3 + s01*s23  (6 pairs)
        u64 sig = f2mul(A[2], A[3]);
        sig = f2fma(A[0], A[1], sig);
        sig = f2fma(s01, s23, sig);

        // products of a, b per half + exclusive-within-half
        u64 pa01 = f2mul(a[0], a[1]), pa23 = f2mul(a[2], a[3]);
        u64 Pa = f2mul(pa01, pa23);                  // (Pa_lo, Pa_hi)
        u64 epa[4] = { f2mul(a[1], pa23), f2mul(a[0], pa23),
                       f2mul(pa01, a[3]), f2mul(pa01, a[2]) };

        u64 pb01 = f2mul(b[0], b[1]), pb23 = f2mul(b[2], b[3]);
        u64 Pb = f2mul(pb01, pb23);
        u64 epb[4] = { f2mul(b[1], pb23), f2mul(b[0], pb23),
                       f2mul(pb01, b[3]), f2mul(pb01, b[2]) };

        // ---- scalar denominator (once per point) ----
        float Sl, Sh, gl, gh, Pal, Pah, Pbl, Pbh;
        upk(Sl, Sh, S); upk(gl, gh, sig);
        upk(Pal, Pah, Pa); upk(Pbl, Pbh, Pb);
        float D1 = fmaf(Sl, Sh, gl + gh);            // all 28 pairs
        float D  = fmaf(0.5f, fmaf(Pal, Pah, Pbl * Pbh), D1);
        float rd = rcp_approx(D);
        u64 rD  = pk(rd, rd);

        // cross-half factors: lo lane needs hi aggregate and vice versa
        u64 Ssw  = swap64(S);
        u64 PaQ  = f2mul(swap64(Pa), cQ);
        u64 PbQ  = f2mul(swap64(Pb), cQ);

        u64 o[4];
#pragma unroll
        for (int d = 0; d < 4; d++) {
            u64 eS    = f2add(eo[d], Ssw);                    // exclSum_d(A)
            u64 ea    = f2mul(epa[d], PaQ);                   // exclProd_d(a)/4
            u64 eb    = f2mul(epb[d], PbQ);                   // exclProd_d(b)/4
            u64 inner = f2fma(b[d], ea, f2mul(a[d], eb));
            u64 num   = f2fma(f2mul(a[d], b[d]), eS, inner);
            o[d] = f2mul(num, rD);
        }

        float o0l, o0h, o1l, o1h, o2l, o2h, o3l, o3h;
        upk(o0l, o0h, o[0]); upk(o1l, o1h, o[1]);
        upk(o2l, o2h, o[2]); upk(o3l, o3h, o[3]);
        o4[2 * p + 0] = make_float4(o0l, o1l, o2l, o3l);
        o4[2 * p + 1] = make_float4(o0h, o1h, o2h, o3h);

        if (!more) break;
        p = pn; v0 = w0; v1 = w1;
    }
}

extern "C" void kernel_launch(void* const* d_in, const int* in_sizes, int n_in,
                              void* d_out, int out_size) {
    const float4* x4 = (const float4*)d_in[0];   // [N, 8] fp32
    float4* o4 = (float4*)d_out;
    int n = in_sizes[0] / 8;
    const int block = 256;

    int per_sm = 4;
    cudaOccupancyMaxActiveBlocksPerMultiprocessor(&per_sm, e8_quantize_kernel, block, 0);
    if (per_sm < 1) per_sm = 1;
    int grid = 148 * per_sm;                     // persistent single wave
    int max_grid = (n + block - 1) / block;
    if (grid > max_grid) grid = max_grid;
    int stride = grid * block;
    e8_quantize_kernel<<<grid, block>>>(x4, o4, n, stride);
}

// round 10
// speedup vs baseline: 1.1684x; 1.1684x over previous
#include <cuda_runtime.h>

// E8 quantizer, closed form, f32x2 packed over the EVEN/ODD dim split.
//
// Math (rounds 1-9): all 240 E8 roots have ||c||^2 = 2, so the softmax of
// -(dist^2)/T reduces to softmax(beta * x.c), beta = 2/0.3, and factorizes:
//  Type-1 (112 roots, +-1 at dims i,j):  A_i = 2cosh(beta x_i)
//     denom1 = sum_{i<j} A_i A_j,  num1_d = (a_d b_d) * exclSum_d(A)
//  Type-2 (128 roots, (+-1/2)^8, even parity): a_i = 2cosh(bx_i/2), b_i = 2sinh(bx_i/2)
//     denom2 = (prod a + prod b)/2, num2_d = (b_d exclProd_d(a) + a_d exclProd_d(b))/4
//  with A = a^2 - 2.  16 EX2 + 1 RCP per point.  All-positive adds /
//  sign-safe muls -> no cancellation; +- root pairs => denom >= 1.
//
// The half-split algebra (R7) holds for ANY partition of the 8 dims into two
// 4-sets.  Picking EVEN dims as the lo lane and ODD dims as the hi lane makes
// every packed pair (x_{2i}, x_{2i+1}) memory-adjacent: the packed operands
// are exactly v0.xy / v0.zw / v1.xy / v1.zw and outputs store back as
// adjacent pairs — the R9 pack/unpack MOV overhead (8% ALU) vanishes.  Only
// three half-swaps (S, Pa, Pb) cross lanes.
//
// Shape lesson (R4/R9 vs R1/R6/R7): under the harness's graph-replay timing,
// oversubscribed simple grids beat persistent 592-CTA waves.  So: 1 point per
// thread, plain grid, no loop (fewer regs, more CTAs/SM).

#define BETA_HALF_LOG2E 4.8089834696568576f   // (2/0.3)/2 * log2(e)

typedef unsigned long long u64;

union F2 { float2 f; u64 u; };

__device__ __forceinline__ float ex2_approx(float x) {
    float y; asm("ex2.approx.ftz.f32 %0, %1;" : "=f"(y) : "f"(x)); return y;
}
__device__ __forceinline__ float rcp_approx(float x) {
    float y; asm("rcp.approx.ftz.f32 %0, %1;" : "=f"(y) : "f"(x)); return y;
}
__device__ __forceinline__ float2 f2fma(float2 a, float2 b, float2 c) {
    F2 A{a}, B{b}, C{c}, R;
    asm("fma.rn.f32x2 %0, %1, %2, %3;" : "=l"(R.u) : "l"(A.u), "l"(B.u), "l"(C.u));
    return R.f;
}
__device__ __forceinline__ float2 f2add(float2 a, float2 b) {
    F2 A{a}, B{b}, R;
    asm("add.rn.f32x2 %0, %1, %2;" : "=l"(R.u) : "l"(A.u), "l"(B.u));
    return R.f;
}
__device__ __forceinline__ float2 f2sub(float2 a, float2 b) {
    F2 A{a}, B{b}, R;
    asm("sub.rn.f32x2 %0, %1, %2;" : "=l"(R.u) : "l"(A.u), "l"(B.u));
    return R.f;
}
__device__ __forceinline__ float2 f2mul(float2 a, float2 b) {
    F2 A{a}, B{b}, R;
    asm("mul.rn.f32x2 %0, %1, %2;" : "=l"(R.u) : "l"(A.u), "l"(B.u));
    return R.f;
}
__device__ __forceinline__ float2 swap2(float2 v) { return make_float2(v.y, v.x); }

__global__ void __launch_bounds__(256) e8_quantize_kernel(
    const float4* __restrict__ x4, float4* __restrict__ o4, int n)
{
    int p = blockIdx.x * blockDim.x + threadIdx.x;
    if (p >= n) return;

    float4 v0 = x4[2 * p + 0];
    float4 v1 = x4[2 * p + 1];

    // packed pairs (even dim, odd dim) — exactly the loaded register pairs
    float2 X[4] = { make_float2(v0.x, v0.y), make_float2(v0.z, v0.w),
                    make_float2(v1.x, v1.y), make_float2(v1.z, v1.w) };

    const float2 cB  = make_float2( BETA_HALF_LOG2E,  BETA_HALF_LOG2E);
    const float2 cN2 = make_float2(-2.0f, -2.0f);

    float2 a[4], b[4], A[4];
#pragma unroll
    for (int i = 0; i < 4; i++) {
        float2 t = f2mul(X[i], cB);
        float2 hp = make_float2(ex2_approx( t.x), ex2_approx( t.y));
        float2 hn = make_float2(ex2_approx(-t.x), ex2_approx(-t.y));
        a[i] = f2add(hp, hn);               // 2cosh(beta x / 2)
        b[i] = f2sub(hp, hn);               // 2sinh(beta x / 2)
        A[i] = f2fma(a[i], a[i], cN2);      // 2cosh(beta x)
    }

    // ---- per-half trees over 4 packed elements (lo=evens, hi=odds) ----
    float2 s01 = f2add(A[0], A[1]), s23 = f2add(A[2], A[3]);
    float2 S = f2add(s01, s23);                       // (S_even, S_odd)
    float2 eo[4] = { f2add(A[1], s23), f2add(A[0], s23),
                     f2add(s01, A[3]), f2add(s01, A[2]) };

    // within-half pair sums (6 pairs each): sig = A0A1 + A2A3 + s01*s23
    float2 sig = f2mul(A[2], A[3]);
    sig = f2fma(A[0], A[1], sig);
    sig = f2fma(s01, s23, sig);

    float2 pa01 = f2mul(a[0], a[1]), pa23 = f2mul(a[2], a[3]);
    float2 Pa = f2mul(pa01, pa23);
    float2 epa[4] = { f2mul(a[1], pa23), f2mul(a[0], pa23),
                      f2mul(pa01, a[3]), f2mul(pa01, a[2]) };

    float2 pb01 = f2mul(b[0], b[1]), pb23 = f2mul(b[2], b[3]);
    float2 Pb = f2mul(pb01, pb23);
    float2 epb[4] = { f2mul(b[1], pb23), f2mul(b[0], pb23),
                      f2mul(pb01, b[3]), f2mul(pb01, b[2]) };

    // ---- scalar denominator, once ----
    float D1 = fmaf(S.x, S.y, sig.x + sig.y);         // all 28 pairs A_iA_j
    float D  = fmaf(0.5f, fmaf(Pa.x, Pa.y, Pb.x * Pb.y), D1);
    float rd = rcp_approx(D);
    float2 rD = make_float2(rd, rd);

    // cross-half aggregates (each lane needs the OTHER half's totals)
    const float2 cQ = make_float2(0.25f, 0.25f);
    float2 Ssw = swap2(S);
    float2 PaQ = f2mul(swap2(Pa), cQ);
    float2 PbQ = f2mul(swap2(Pb), cQ);

    float2 o[4];
#pragma unroll
    for (int d = 0; d < 4; d++) {
        float2 eS    = f2add(eo[d], Ssw);             // exclSum_d(A)
        float2 ea    = f2mul(epa[d], PaQ);            // exclProd_d(a)/4
        float2 eb    = f2mul(epb[d], PbQ);            // exclProd_d(b)/4
        float2 inner = f2fma(b[d], ea, f2mul(a[d], eb));
        float2 num   = f2fma(f2mul(a[d], b[d]), eS, inner);
        o[d] = f2mul(num, rD);
    }

    // packed pairs are already (even,odd) = memory order: direct stores
    o4[2 * p + 0] = make_float4(o[0].x, o[0].y, o[1].x, o[1].y);
    o4[2 * p + 1] = make_float4(o[2].x, o[2].y, o[3].x, o[3].y);
}

extern "C" void kernel_launch(void* const* d_in, const int* in_sizes, int n_in,
                              void* d_out, int out_size) {
    const float4* x4 = (const float4*)d_in[0];   // [N, 8] fp32
    float4* o4 = (float4*)d_out;
    int n = in_sizes[0] / 8;
    const int block = 256;
    int grid = (n + block - 1) / block;
    e8_quantize_kernel<<<grid, block>>>(x4, o4, n);
}